// round 1
// baseline (speedup 1.0000x reference)
#include <cuda_runtime.h>
#include <cstdint>

// RandomPixelMapping: out[b,c,y,x] = table[b,c, clip(rint(x*255), 0, 255)]
// x: [64,3,512,512] f32, table: [64,3,256] f32, out: [64,3,512,512] f32.
// Pure HBM-streaming gather; per-(b,c) 256-entry LUT kept in shared memory.

#define PLANE_ELEMS   (512 * 512)          // 262144 elems per (b,c) plane
#define VEC_PER_PLANE (PLANE_ELEMS / 4)    // 65536 float4
#define THREADS       256
#define CHUNKS        64                   // blocks per plane
#define VEC_PER_BLOCK (VEC_PER_PLANE / CHUNKS)        // 1024 float4 per block
#define VEC_PER_THREAD (VEC_PER_BLOCK / THREADS)      // 4 float4 per thread

__global__ __launch_bounds__(THREADS)
void RandomPixelMapping_19593640805006_kernel(
    const float4* __restrict__ x,
    const float*  __restrict__ table,
    float4*       __restrict__ out)
{
    __shared__ float lut[256];

    const int plane = blockIdx.y;                 // 0..191  (b*3 + c)
    // cooperative LUT fill: 256 threads -> 256 entries
    lut[threadIdx.x] = table[plane * 256 + threadIdx.x];
    __syncthreads();

    const size_t base = (size_t)plane * VEC_PER_PLANE
                      + (size_t)blockIdx.x * VEC_PER_BLOCK
                      + threadIdx.x;

    // Front-batch the 4 independent vec4 loads for MLP, then gather, then store.
    float4 v[VEC_PER_THREAD];
#pragma unroll
    for (int j = 0; j < VEC_PER_THREAD; ++j)
        v[j] = x[base + (size_t)j * THREADS];

#pragma unroll
    for (int j = 0; j < VEC_PER_THREAD; ++j) {
        float4 r;
        int i0 = __float2int_rn(v[j].x * 255.0f);
        int i1 = __float2int_rn(v[j].y * 255.0f);
        int i2 = __float2int_rn(v[j].z * 255.0f);
        int i3 = __float2int_rn(v[j].w * 255.0f);
        i0 = min(max(i0, 0), 255);
        i1 = min(max(i1, 0), 255);
        i2 = min(max(i2, 0), 255);
        i3 = min(max(i3, 0), 255);
        r.x = lut[i0];
        r.y = lut[i1];
        r.z = lut[i2];
        r.w = lut[i3];
        out[base + (size_t)j * THREADS] = r;
    }
}

extern "C" void kernel_launch(void* const* d_in, const int* in_sizes, int n_in,
                              void* d_out, int out_size)
{
    const float4* x     = (const float4*)d_in[0];
    const float*  table = (const float*) d_in[1];
    float4*       out   = (float4*)d_out;

    dim3 grid(CHUNKS, 64 * 3);   // 64 chunks x 192 planes
    RandomPixelMapping_19593640805006_kernel<<<grid, THREADS>>>(x, table, out);
}